// round 3
// baseline (speedup 1.0000x reference)
#include <cuda_runtime.h>
#include <cuda_bf16.h>

// Problem constants (fixed by the reference setup).
#define BB   256
#define NN   4000
#define GG   50
#define M_TOT (BB * NN)      // 1,024,000 elements
#define TMAX  (BB * GG)      // 12,800 max TPs per threshold
#define NBKT  256

// ----------------------------------------------------------------------------
// Device scratch (static globals — no allocation allowed)
// ----------------------------------------------------------------------------
__device__ unsigned char      g_tp[M_TOT];           // per-element TP bits (bit0: thr .5, bit1: thr .75)
__device__ unsigned long long g_list[2][TMAX];       // compacted TP keys (unordered)
__device__ unsigned long long g_btmp[2][TMAX];       // bucketed (unsorted within bucket)
__device__ unsigned long long g_sorted[2][TMAX];     // fully sorted ascending key
__device__ int g_T[2];                               // TP counts
__device__ int g_bcount[2][NBKT];
__device__ int g_boff[2][NBKT + 1];
__device__ int g_bfill[2][NBKT];
__device__ int g_c[2][TMAX + 1];                     // lower-bound histogram

// ----------------------------------------------------------------------------
// Key construction: ascending key == (conf descending, index ascending).
// Low byte carries the value-based bucket (monotone non-decreasing with key).
// ----------------------------------------------------------------------------
__device__ __forceinline__ unsigned int ford(float f) {
    unsigned int u = __float_as_uint(f);
    return (u & 0x80000000u) ? ~u : (u | 0x80000000u);   // ascending float order
}
__device__ __forceinline__ int bucket_of(float conf) {
    int bi = (int)(conf * 256.0f);
    bi = bi < 0 ? 0 : (bi > 255 ? 255 : bi);
    return 255 - bi;                                      // higher conf -> smaller bucket
}
__device__ __forceinline__ unsigned long long make_key(float conf, int idx) {
    unsigned int kh = ~ford(conf);                        // ascending kh == descending conf
    return ((unsigned long long)kh << 32)
         | ((unsigned long long)(unsigned int)idx << 8)
         | (unsigned long long)bucket_of(conf);
}

// ----------------------------------------------------------------------------
// K0: zero the per-launch counters/histograms
// ----------------------------------------------------------------------------
__global__ void k_zero() {
    int i = blockIdx.x * blockDim.x + threadIdx.x;
    if (i < 2 * (TMAX + 1)) ((int*)g_c)[i] = 0;
    if (i < 2) g_T[i] = 0;
    if (i < 2 * NBKT) { ((int*)g_bcount)[i] = 0; ((int*)g_bfill)[i] = 0; }
}

// ----------------------------------------------------------------------------
// K1: greedy matching per batch. Replicates:
//   for each gt g (in order): claim lowest-index unused proposal with iou > thr
// pot bitmaps stored transposed [z][g][word-of-n] so each greedy step is a
// 125-word scan + shared atomicMin.
// ----------------------------------------------------------------------------
__global__ void __launch_bounds__(256) k_greedy(const float2* __restrict__ segs,
                                                const float2* __restrict__ gts) {
    const int b = blockIdx.x, tid = threadIdx.x;
    extern __shared__ unsigned int pot[];                 // [2][GG][125]
    __shared__ unsigned int used[2][125];
    __shared__ float2 sg[GG];
    __shared__ int s_min;

    if (tid < GG) sg[tid] = gts[b * GG + tid];
    for (int i = tid; i < 2 * GG * 125; i += 256) pot[i] = 0u;
    if (tid < 125) { used[0][tid] = 0u; used[1][tid] = 0u; }
    __syncthreads();

    // candidate bitmaps
    for (int n = tid; n < NN; n += 256) {
        float2 s = segs[b * NN + n];
        float la = s.y - s.x;
        unsigned int wbit = 1u << (n & 31);
        int w = n >> 5;
#pragma unroll 5
        for (int g = 0; g < GG; ++g) {
            float2 t = sg[g];
            float inter = fminf(s.y, t.y) - fmaxf(s.x, t.x);
            inter = fmaxf(inter, 0.0f);
            float uni = la + (t.y - t.x) - inter;
            float iou = inter / uni;
            if (iou > 0.5f)  atomicOr(&pot[(0 * GG + g) * 125 + w], wbit);
            if (iou > 0.75f) atomicOr(&pot[(1 * GG + g) * 125 + w], wbit);
        }
    }
    __syncthreads();

    // greedy claims
    for (int z = 0; z < 2; ++z) {
        for (int g = 0; g < GG; ++g) {
            if (tid == 0) s_min = NN;
            __syncthreads();
            if (tid < 125) {
                unsigned int cand = pot[(z * GG + g) * 125 + tid] & ~used[z][tid];
                if (cand) atomicMin(&s_min, tid * 32 + __ffs((int)cand) - 1);
            }
            __syncthreads();
            if (tid == 0 && s_min < NN) used[z][s_min >> 5] |= 1u << (s_min & 31);
            __syncthreads();
        }
    }

    for (int n = tid; n < NN; n += 256) {
        unsigned int b0 = (used[0][n >> 5] >> (n & 31)) & 1u;
        unsigned int b1 = (used[1][n >> 5] >> (n & 31)) & 1u;
        g_tp[b * NN + n] = (unsigned char)(b0 | (b1 << 1));
    }
}

// ----------------------------------------------------------------------------
// K2: compact TP keys + bucket counts
// ----------------------------------------------------------------------------
__global__ void k_compact(const float* __restrict__ scores) {
    int idx = blockIdx.x * blockDim.x + threadIdx.x;
    if (idx >= M_TOT) return;
    unsigned char tpb = g_tp[idx];
    if (!tpb) return;
    float conf = scores[idx];
    unsigned long long key = make_key(conf, idx);
    int bk = (int)(key & 0xFFull);
    if (tpb & 1) { int p = atomicAdd(&g_T[0], 1); g_list[0][p] = key; atomicAdd(&g_bcount[0][bk], 1); }
    if (tpb & 2) { int p = atomicAdd(&g_T[1], 1); g_list[1][p] = key; atomicAdd(&g_bcount[1][bk], 1); }
}

// K3a: scan bucket counts (tiny)
__global__ void k_bscan() {
    int z = threadIdx.x;
    if (z < 2) {
        int acc = 0;
        for (int i = 0; i < NBKT; ++i) { g_boff[z][i] = acc; acc += g_bcount[z][i]; }
        g_boff[z][NBKT] = acc;
    }
}

// K3b: scatter keys into their buckets
__global__ void k_scatter() {
    int z = blockIdx.y;
    int i = blockIdx.x * blockDim.x + threadIdx.x;
    if (i >= g_T[z]) return;
    unsigned long long key = g_list[z][i];
    int bk = (int)(key & 0xFFull);
    int slot = atomicAdd(&g_bfill[z][bk], 1);
    g_btmp[z][g_boff[z][bk] + slot] = key;
}

// K3c: rank-sort within each bucket (k ~ 50 => O(k^2) trivial)
__global__ void k_bsort() {
    int z = blockIdx.y, bk = blockIdx.x;
    int st = g_boff[z][bk], en = g_boff[z][bk + 1];
    int cnt = en - st;
    for (int i = threadIdx.x; i < cnt; i += blockDim.x) {
        unsigned long long k = g_btmp[z][st + i];
        int r = 0;
        for (int j = 0; j < cnt; ++j) r += (g_btmp[z][st + j] < k) ? 1 : 0;
        g_sorted[z][st + r] = k;
    }
}

// ----------------------------------------------------------------------------
// K4: each of the 1M elements binary-searches its lower-bound position in the
// sorted TP key array (cached in SMEM), histogramming into g_c.
// rank of TP q (elements strictly ahead of it) = prefix(c)[q] - 1.
// ----------------------------------------------------------------------------
__global__ void __launch_bounds__(1024) k_hist(const float* __restrict__ scores) {
    int z = blockIdx.y;
    extern __shared__ unsigned long long sk[];
    int T = g_T[z];
    for (int i = threadIdx.x; i < T; i += 1024) sk[i] = g_sorted[z][i];
    __syncthreads();
    int stride = gridDim.x * 1024;
    for (int idx = blockIdx.x * 1024 + threadIdx.x; idx < M_TOT; idx += stride) {
        unsigned long long key = make_key(scores[idx], idx);
        int lo = 0, hi = T;
        while (lo < hi) {
            int mid = (lo + hi) >> 1;
            if (sk[mid] < key) lo = mid + 1; else hi = mid;
        }
        atomicAdd(&g_c[z][lo], 1);
    }
}

// ----------------------------------------------------------------------------
// K5: finalize AP per threshold.
//   C[q]     = inclusive prefix of c  -> rank_q + 1
//   prec_q   = (q+1)/C[q]
//   suffmax  over q; sum; subtract rank-0 TP's term iff C[0]==1
// ----------------------------------------------------------------------------
__global__ void __launch_bounds__(1024) k_final(float* __restrict__ out) {
    int z = blockIdx.x, tid = threadIdx.x;
    extern __shared__ float smf[];
    float*  prec = smf;                                   // TMAX floats
    int*    auxi = (int*)(smf + TMAX);                    // 1024
    float*  auxf = (float*)(auxi + 1024);                 // 1024
    double* auxd = (double*)(auxf + 1024);                // 1024 (8B aligned: offset 59392)

    int T = g_T[z];
    if (T == 0) { if (tid == 0) out[z] = 0.0f; return; }
    int bins = T + 1;

    // inclusive prefix sum of g_c over [0, bins)
    int CH = (bins + 1023) >> 10;
    int st = min(tid * CH, bins), en = min(st + CH, bins);
    int ssum = 0;
    for (int p = st; p < en; ++p) ssum += g_c[z][p];
    auxi[tid] = ssum;
    __syncthreads();
    if (tid == 0) {
        int acc = 0;
        for (int i = 0; i < 1024; ++i) { int v = auxi[i]; auxi[i] = acc; acc += v; }
    }
    __syncthreads();
    int C = auxi[tid];
    for (int p = st; p < en; ++p) {
        C += g_c[z][p];
        if (p < T) prec[p] = (float)(p + 1) / (float)C;
    }
    __syncthreads();

    // suffix max over [0, T) + weighted sum
    int CH2 = (T + 1023) >> 10;
    int st2 = min(tid * CH2, T), en2 = min(st2 + CH2, T);
    float mx = 0.0f;
    for (int i = st2; i < en2; ++i) mx = fmaxf(mx, prec[i]);
    auxf[tid] = mx;
    __syncthreads();
    if (tid == 0) {
        float acc = 0.0f;
        for (int i = 1023; i >= 0; --i) { float v = auxf[i]; auxf[i] = acc; acc = fmaxf(acc, v); }
    }
    __syncthreads();
    float run = auxf[tid];
    double s = 0.0;
    float m0 = 0.0f;
    for (int i = en2 - 1; i >= st2; --i) {
        run = fmaxf(run, prec[i]);
        s += (double)run;
        if (i == 0) m0 = run;   // global max precision (only reached by tid 0)
    }
    auxd[tid] = s;
    __syncthreads();
    for (int off = 512; off; off >>= 1) {
        if (tid < off) auxd[tid] += auxd[tid + off];
        __syncthreads();
    }
    if (tid == 0) {
        double tot = auxd[0];
        if (g_c[z][0] == 1) tot -= (double)m0;  // TP at global sorted position 0 is excluded
        out[z] = (float)(tot / (double)(BB * GG));
    }
}

// ----------------------------------------------------------------------------
// Launcher (graph-capturable: kernels only, default stream)
// ----------------------------------------------------------------------------
extern "C" void kernel_launch(void* const* d_in, const int* in_sizes, int n_in,
                              void* d_out, int out_size) {
    const float*  scores = (const float*)d_in[0];
    const float2* segs   = (const float2*)d_in[1];
    const float2* gts    = (const float2*)d_in[2];
    float* out = (float*)d_out;

    cudaFuncSetAttribute(k_greedy, cudaFuncAttributeMaxDynamicSharedMemorySize, 2 * GG * 125 * 4);
    cudaFuncSetAttribute(k_hist,   cudaFuncAttributeMaxDynamicSharedMemorySize, TMAX * 8);
    cudaFuncSetAttribute(k_final,  cudaFuncAttributeMaxDynamicSharedMemorySize,
                         TMAX * 4 + 1024 * 4 + 1024 * 4 + 1024 * 8);

    k_zero<<<(2 * (TMAX + 1) + 1023) / 1024, 1024>>>();
    k_greedy<<<BB, 256, 2 * GG * 125 * 4>>>(segs, gts);
    k_compact<<<(M_TOT + 255) / 256, 256>>>(scores);
    k_bscan<<<1, 32>>>();
    k_scatter<<<dim3((TMAX + 255) / 256, 2), 256>>>();
    k_bsort<<<dim3(NBKT, 2), 128>>>();
    k_hist<<<dim3(148, 2), 1024, TMAX * 8>>>(scores);
    k_final<<<2, 1024, TMAX * 4 + 1024 * 4 + 1024 * 4 + 1024 * 8>>>(out);
}

// round 4
// speedup vs baseline: 1.0070x; 1.0070x over previous
#include <cuda_runtime.h>
#include <cuda_bf16.h>

// Problem constants (fixed by the reference setup).
#define BB   256
#define NN   4000
#define GG   50
#define M_TOT (BB * NN)      // 1,024,000 elements
#define TMAX  (BB * GG)      // 12,800 max TPs per threshold
#define NBKT  256

// ----------------------------------------------------------------------------
// Device scratch (static globals — no allocation allowed)
// ----------------------------------------------------------------------------
__device__ unsigned char      g_tp[M_TOT];           // per-element TP bits (bit0: thr .5, bit1: thr .75)
__device__ unsigned long long g_list[2][TMAX];       // compacted TP keys (unordered)
__device__ unsigned long long g_btmp[2][TMAX];       // bucketed (unsorted within bucket)
__device__ unsigned long long g_sorted[2][TMAX];     // fully sorted ascending key
__device__ int g_T[2];                               // TP counts
__device__ int g_bcount[2][NBKT];
__device__ int g_boff[2][NBKT + 1];
__device__ int g_bfill[2][NBKT];
__device__ int g_c[2][TMAX + 1];                     // lower-bound histogram

// ----------------------------------------------------------------------------
// Key construction: ascending key == (conf descending, index ascending).
// Low byte carries the value-based bucket (monotone non-decreasing with key).
// ----------------------------------------------------------------------------
__device__ __forceinline__ unsigned int ford(float f) {
    unsigned int u = __float_as_uint(f);
    return (u & 0x80000000u) ? ~u : (u | 0x80000000u);   // ascending float order
}
__device__ __forceinline__ int bucket_of(float conf) {
    int bi = (int)(conf * 256.0f);
    bi = bi < 0 ? 0 : (bi > 255 ? 255 : bi);
    return 255 - bi;                                      // higher conf -> smaller bucket
}
__device__ __forceinline__ unsigned long long make_key(float conf, int idx) {
    unsigned int kh = ~ford(conf);                        // ascending kh == descending conf
    return ((unsigned long long)kh << 32)
         | ((unsigned long long)(unsigned int)idx << 8)
         | (unsigned long long)bucket_of(conf);
}

// ----------------------------------------------------------------------------
// K0: zero the per-launch counters/histograms
// ----------------------------------------------------------------------------
__global__ void k_zero() {
    int i = blockIdx.x * blockDim.x + threadIdx.x;
    if (i < 2 * (TMAX + 1)) ((int*)g_c)[i] = 0;
    if (i < 2) g_T[i] = 0;
    if (i < 2 * NBKT) { ((int*)g_bcount)[i] = 0; ((int*)g_bfill)[i] = 0; }
}

// ----------------------------------------------------------------------------
// K1: greedy matching per batch. Replicates:
//   for each gt g (in order): claim lowest-index unused proposal with iou > thr
// pot bitmaps stored transposed [z][g][word-of-n] so each greedy step is a
// 125-word scan + shared atomicMin.
// ----------------------------------------------------------------------------
__global__ void __launch_bounds__(256) k_greedy(const float2* __restrict__ segs,
                                                const float2* __restrict__ gts) {
    const int b = blockIdx.x, tid = threadIdx.x;
    extern __shared__ unsigned int pot[];                 // [2][GG][125]
    __shared__ unsigned int used[2][125];
    __shared__ float2 sg[GG];
    __shared__ int s_min;

    if (tid < GG) sg[tid] = gts[b * GG + tid];
    for (int i = tid; i < 2 * GG * 125; i += 256) pot[i] = 0u;
    if (tid < 125) { used[0][tid] = 0u; used[1][tid] = 0u; }
    __syncthreads();

    // candidate bitmaps
    for (int n = tid; n < NN; n += 256) {
        float2 s = segs[b * NN + n];
        float la = s.y - s.x;
        unsigned int wbit = 1u << (n & 31);
        int w = n >> 5;
#pragma unroll 5
        for (int g = 0; g < GG; ++g) {
            float2 t = sg[g];
            float inter = fminf(s.y, t.y) - fmaxf(s.x, t.x);
            inter = fmaxf(inter, 0.0f);
            float uni = la + (t.y - t.x) - inter;
            float iou = inter / uni;
            if (iou > 0.5f)  atomicOr(&pot[(0 * GG + g) * 125 + w], wbit);
            if (iou > 0.75f) atomicOr(&pot[(1 * GG + g) * 125 + w], wbit);
        }
    }
    __syncthreads();

    // greedy claims
    for (int z = 0; z < 2; ++z) {
        for (int g = 0; g < GG; ++g) {
            if (tid == 0) s_min = NN;
            __syncthreads();
            if (tid < 125) {
                unsigned int cand = pot[(z * GG + g) * 125 + tid] & ~used[z][tid];
                if (cand) atomicMin(&s_min, tid * 32 + __ffs((int)cand) - 1);
            }
            __syncthreads();
            if (tid == 0 && s_min < NN) used[z][s_min >> 5] |= 1u << (s_min & 31);
            __syncthreads();
        }
    }

    for (int n = tid; n < NN; n += 256) {
        unsigned int b0 = (used[0][n >> 5] >> (n & 31)) & 1u;
        unsigned int b1 = (used[1][n >> 5] >> (n & 31)) & 1u;
        g_tp[b * NN + n] = (unsigned char)(b0 | (b1 << 1));
    }
}

// ----------------------------------------------------------------------------
// K2: compact TP keys + bucket counts
// ----------------------------------------------------------------------------
__global__ void k_compact(const float* __restrict__ scores) {
    int idx = blockIdx.x * blockDim.x + threadIdx.x;
    if (idx >= M_TOT) return;
    unsigned char tpb = g_tp[idx];
    if (!tpb) return;
    float conf = scores[idx];
    unsigned long long key = make_key(conf, idx);
    int bk = (int)(key & 0xFFull);
    if (tpb & 1) { int p = atomicAdd(&g_T[0], 1); g_list[0][p] = key; atomicAdd(&g_bcount[0][bk], 1); }
    if (tpb & 2) { int p = atomicAdd(&g_T[1], 1); g_list[1][p] = key; atomicAdd(&g_bcount[1][bk], 1); }
}

// K3a: scan bucket counts (tiny)
__global__ void k_bscan() {
    int z = threadIdx.x;
    if (z < 2) {
        int acc = 0;
        for (int i = 0; i < NBKT; ++i) { g_boff[z][i] = acc; acc += g_bcount[z][i]; }
        g_boff[z][NBKT] = acc;
    }
}

// K3b: scatter keys into their buckets
__global__ void k_scatter() {
    int z = blockIdx.y;
    int i = blockIdx.x * blockDim.x + threadIdx.x;
    if (i >= g_T[z]) return;
    unsigned long long key = g_list[z][i];
    int bk = (int)(key & 0xFFull);
    int slot = atomicAdd(&g_bfill[z][bk], 1);
    g_btmp[z][g_boff[z][bk] + slot] = key;
}

// K3c: rank-sort within each bucket (k ~ 50 => O(k^2) trivial)
__global__ void k_bsort() {
    int z = blockIdx.y, bk = blockIdx.x;
    int st = g_boff[z][bk], en = g_boff[z][bk + 1];
    int cnt = en - st;
    for (int i = threadIdx.x; i < cnt; i += blockDim.x) {
        unsigned long long k = g_btmp[z][st + i];
        int r = 0;
        for (int j = 0; j < cnt; ++j) r += (g_btmp[z][st + j] < k) ? 1 : 0;
        g_sorted[z][st + r] = k;
    }
}

// ----------------------------------------------------------------------------
// K4: each of the 1M elements binary-searches its lower-bound position in the
// sorted TP key array (cached in SMEM), histogramming into g_c.
// rank of TP q (elements strictly ahead of it) = prefix(c)[q] - 1.
// ----------------------------------------------------------------------------
__global__ void __launch_bounds__(1024) k_hist(const float* __restrict__ scores) {
    int z = blockIdx.y;
    extern __shared__ unsigned long long sk[];
    int T = g_T[z];
    for (int i = threadIdx.x; i < T; i += 1024) sk[i] = g_sorted[z][i];
    __syncthreads();
    int stride = gridDim.x * 1024;
    for (int idx = blockIdx.x * 1024 + threadIdx.x; idx < M_TOT; idx += stride) {
        unsigned long long key = make_key(scores[idx], idx);
        int lo = 0, hi = T;
        while (lo < hi) {
            int mid = (lo + hi) >> 1;
            if (sk[mid] < key) lo = mid + 1; else hi = mid;
        }
        atomicAdd(&g_c[z][lo], 1);
    }
}

// ----------------------------------------------------------------------------
// K5: finalize AP per threshold.
//   C[q]     = inclusive prefix of c  -> rank_q + 1
//   prec_q   = (q+1)/C[q]
//   suffmax  over q; sum; subtract rank-0 TP's term iff C[0]==1
// ----------------------------------------------------------------------------
__global__ void __launch_bounds__(1024) k_final(float* __restrict__ out) {
    int z = blockIdx.x, tid = threadIdx.x;
    extern __shared__ float smf[];
    float*  prec = smf;                                   // TMAX floats
    int*    auxi = (int*)(smf + TMAX);                    // 1024
    float*  auxf = (float*)(auxi + 1024);                 // 1024
    double* auxd = (double*)(auxf + 1024);                // 1024 (8B aligned: offset 59392)

    int T = g_T[z];
    if (T == 0) { if (tid == 0) out[z] = 0.0f; return; }
    int bins = T + 1;

    // inclusive prefix sum of g_c over [0, bins)
    int CH = (bins + 1023) >> 10;
    int st = min(tid * CH, bins), en = min(st + CH, bins);
    int ssum = 0;
    for (int p = st; p < en; ++p) ssum += g_c[z][p];
    auxi[tid] = ssum;
    __syncthreads();
    if (tid == 0) {
        int acc = 0;
        for (int i = 0; i < 1024; ++i) { int v = auxi[i]; auxi[i] = acc; acc += v; }
    }
    __syncthreads();
    int C = auxi[tid];
    for (int p = st; p < en; ++p) {
        C += g_c[z][p];
        if (p < T) prec[p] = (float)(p + 1) / (float)C;
    }
    __syncthreads();

    // suffix max over [0, T) + weighted sum
    int CH2 = (T + 1023) >> 10;
    int st2 = min(tid * CH2, T), en2 = min(st2 + CH2, T);
    float mx = 0.0f;
    for (int i = st2; i < en2; ++i) mx = fmaxf(mx, prec[i]);
    auxf[tid] = mx;
    __syncthreads();
    if (tid == 0) {
        float acc = 0.0f;
        for (int i = 1023; i >= 0; --i) { float v = auxf[i]; auxf[i] = acc; acc = fmaxf(acc, v); }
    }
    __syncthreads();
    float run = auxf[tid];
    double s = 0.0;
    float m0 = 0.0f;
    for (int i = en2 - 1; i >= st2; --i) {
        run = fmaxf(run, prec[i]);
        s += (double)run;
        if (i == 0) m0 = run;   // global max precision (only reached by tid 0)
    }
    auxd[tid] = s;
    __syncthreads();
    for (int off = 512; off; off >>= 1) {
        if (tid < off) auxd[tid] += auxd[tid + off];
        __syncthreads();
    }
    if (tid == 0) {
        double tot = auxd[0];
        if (g_c[z][0] == 1) tot -= (double)m0;  // TP at global sorted position 0 is excluded
        out[z] = (float)(tot / (double)(BB * GG));
    }
}

// ----------------------------------------------------------------------------
// Launcher (graph-capturable: kernels only, default stream)
// ----------------------------------------------------------------------------
extern "C" void kernel_launch(void* const* d_in, const int* in_sizes, int n_in,
                              void* d_out, int out_size) {
    const float*  scores = (const float*)d_in[0];
    const float2* segs   = (const float2*)d_in[1];
    const float2* gts    = (const float2*)d_in[2];
    float* out = (float*)d_out;

    cudaFuncSetAttribute(k_greedy, cudaFuncAttributeMaxDynamicSharedMemorySize, 2 * GG * 125 * 4);
    cudaFuncSetAttribute(k_hist,   cudaFuncAttributeMaxDynamicSharedMemorySize, TMAX * 8);
    cudaFuncSetAttribute(k_final,  cudaFuncAttributeMaxDynamicSharedMemorySize,
                         TMAX * 4 + 1024 * 4 + 1024 * 4 + 1024 * 8);

    k_zero<<<(2 * (TMAX + 1) + 1023) / 1024, 1024>>>();
    k_greedy<<<BB, 256, 2 * GG * 125 * 4>>>(segs, gts);
    k_compact<<<(M_TOT + 255) / 256, 256>>>(scores);
    k_bscan<<<1, 32>>>();
    k_scatter<<<dim3((TMAX + 255) / 256, 2), 256>>>();
    k_bsort<<<dim3(NBKT, 2), 128>>>();
    k_hist<<<dim3(148, 2), 1024, TMAX * 8>>>(scores);
    k_final<<<2, 1024, TMAX * 4 + 1024 * 4 + 1024 * 4 + 1024 * 8>>>(out);
}